// round 4
// baseline (speedup 1.0000x reference)
#include <cuda_runtime.h>
#include <math.h>

#define B 8
#define C 256
#define H 128
#define W 128
#define OH 65
#define OW 65
#define HW (H*W)          // 16384
#define OHW (OH*OW)       // 4225
#define NPIX (B*OHW)      // 33800 output pixels
#define CPT 4             // channels per thread in gather kernel
#define CG (C/CPT)        // 64 channel groups
#define PAIRS 33          // ceil(OW/2) pixel pairs per output row
#define SPLIT 8           // channel splits in norm kernel
#define CPS (C/SPLIT)     // 32 channels per split

// Scratch: device globals (no allocation allowed)
__device__ float g_part[SPLIT*B*HW];     // 4 MB, partial sum-of-squares
__device__ float g_norm[B*HW];           // 512 KB
__device__ float g_wts[9*NPIX];          // ~1.22 MB, layout [k][b][oy][ox]

// ---------------------------------------------------------------------------
// Kernel 1: partial channel sum-of-squares, float4 loads, 8-way channel split.
// ---------------------------------------------------------------------------
__global__ __launch_bounds__(128) void norm_part_kernel(const float* __restrict__ x) {
    int t   = threadIdx.x;
    int w4  = t & 31;            // float4 index in row (32 per row)
    int hl  = t >> 5;            // local row 0..3
    int bh4 = blockIdx.x;        // 0..B*H/4-1
    int b   = bh4 >> 5;          // H/4 = 32 row-groups per b
    int h   = ((bh4 & 31) << 2) + hl;
    int c0  = blockIdx.y * CPS;

    const float4* p = (const float4*)(x + ((size_t)(b * C + c0)) * HW + (size_t)h * W) + w4;

    float sx = 0.f, sy = 0.f, sz = 0.f, sw = 0.f;
    #pragma unroll 8
    for (int c = 0; c < CPS; c++) {
        float4 v = p[(size_t)c * (HW / 4)];
        sx = fmaf(v.x, v.x, sx);
        sy = fmaf(v.y, v.y, sy);
        sz = fmaf(v.z, v.z, sz);
        sw = fmaf(v.w, v.w, sw);
    }

    float4 o = make_float4(sx, sy, sz, sw);
    ((float4*)g_part)[(size_t)blockIdx.y * (B * HW / 4) + ((size_t)(b * H + h) * W) / 4 + w4] = o;
}

// ---------------------------------------------------------------------------
// Kernel 2: reduce partials + sqrt -> g_norm.
// ---------------------------------------------------------------------------
__global__ __launch_bounds__(256) void norm_reduce_kernel() {
    int i = blockIdx.x * blockDim.x + threadIdx.x;
    if (i >= B * HW / 4) return;
    const float4* p = (const float4*)g_part;
    float4 a = p[i];
    #pragma unroll
    for (int s = 1; s < SPLIT; s++) {
        float4 v = p[(size_t)s * (B * HW / 4) + i];
        a.x += v.x; a.y += v.y; a.z += v.z; a.w += v.w;
    }
    a.x = sqrtf(a.x); a.y = sqrtf(a.y); a.z = sqrtf(a.z); a.w = sqrtf(a.w);
    ((float4*)g_norm)[i] = a;
}

// ---------------------------------------------------------------------------
// Kernel 3: softmax weights over 3x3 window of norms (zero-padded).
// wts layout transposed: [k][pixel] for coalesced gather-side loads.
// ---------------------------------------------------------------------------
__global__ __launch_bounds__(256) void wts_kernel() {
    int idx = blockIdx.x * blockDim.x + threadIdx.x;
    if (idx >= NPIX) return;
    int ox = idx % OW;
    int t  = idx / OW;
    int oy = t % OH;
    int b  = t / OH;

    int iy0 = 2 * oy - 2;
    int ix0 = 2 * ox - 2;

    float v[9];
    #pragma unroll
    for (int i = 0; i < 3; i++) {
        int iy = iy0 + i;
        bool rok = (unsigned)iy < (unsigned)H;
        #pragma unroll
        for (int j = 0; j < 3; j++) {
            int ix = ix0 + j;
            bool ok = rok && ((unsigned)ix < (unsigned)W);
            v[i * 3 + j] = ok ? g_norm[(b * H + iy) * W + ix] : 0.f;
        }
    }

    float m = v[0];
    #pragma unroll
    for (int k = 1; k < 9; k++) m = fmaxf(m, v[k]);

    float e[9];
    float sum = 0.f;
    #pragma unroll
    for (int k = 0; k < 9; k++) {
        e[k] = expf(v[k] - m);
        sum += e[k];
    }
    float inv = 1.f / sum;

    #pragma unroll
    for (int k = 0; k < 9; k++) g_wts[k * NPIX + idx] = e[k] * inv;
}

// ---------------------------------------------------------------------------
// Kernel 4: paired-pixel weighted gather. Thread = (b, cg, oy, pixel-pair).
// Two adjacent output pixels share two aligned float4 loads per (row,channel):
// cols [4p-4..4p-1] (A) and [4p..4p+3] (Bv). Taps: px0 = A.z,A.w,Bv.x ;
// px1 = Bv.x,Bv.y,Bv.z. Pads handled by base-clamp + weight-zeroing.
// ---------------------------------------------------------------------------
__global__ __launch_bounds__(128) void gather_kernel(const float* __restrict__ x,
                                                     float* __restrict__ out) {
    const int TOTAL = B * CG * OH * PAIRS;
    int lin = blockIdx.x * blockDim.x + threadIdx.x;
    int idx = (TOTAL - 1) - lin;                     // reversed traversal (L2 residue)

    int oxp = idx % PAIRS;
    int t   = idx / PAIRS;
    int oy  = t % OH;
    t       = t / OH;
    int cg  = t % CG;
    int b   = t / CG;

    int ox0  = 2 * oxp;
    bool has1 = (oxp < PAIRS - 1);                   // ox1=65 invalid at oxp=32

    int pix0 = (b * OH + oy) * OW + ox0;
    float w0[9], w1[9];
    #pragma unroll
    for (int k = 0; k < 9; k++) {
        w0[k] = g_wts[k * NPIX + pix0];
        w1[k] = has1 ? g_wts[k * NPIX + pix0 + 1] : 0.f;
    }

    // Column base clamps + pad weight zeroing.
    int base0 = 4 * oxp - 4;
    if (oxp == 0) {                 // px0 taps j0 (col -2), j1 (col -1) are pads
        base0 = 0;
        w0[0] = w0[1] = 0.f; w0[3] = w0[4] = 0.f; w0[6] = w0[7] = 0.f;
    }
    int base1 = 4 * oxp;
    if (base1 > W - 4) {            // oxp == 32: px0 tap j2 (col 128) is pad
        base1 = W - 4;
        w0[2] = w0[5] = w0[8] = 0.f;
    }

    // Row clamps + pad weight zeroing (shared by both pixels).
    int iy0 = 2 * oy - 2;
    int iyv[3];
    #pragma unroll
    for (int i = 0; i < 3; i++) {
        int iy = iy0 + i;
        if (iy < 0)       { iy = 0;     w0[i*3]=w0[i*3+1]=w0[i*3+2]=0.f; w1[i*3]=w1[i*3+1]=w1[i*3+2]=0.f; }
        else if (iy >= H) { iy = H - 1; w0[i*3]=w0[i*3+1]=w0[i*3+2]=0.f; w1[i*3]=w1[i*3+1]=w1[i*3+2]=0.f; }
        iyv[i] = iy;
    }

    float acc0[CPT], acc1[CPT];
    #pragma unroll
    for (int k = 0; k < CPT; k++) { acc0[k] = 0.f; acc1[k] = 0.f; }

    const float* xb = x + (size_t)(b * C + cg * CPT) * HW;

    #pragma unroll
    for (int i = 0; i < 3; i++) {
        const float* rp = xb + iyv[i] * W;
        float4 A[CPT], Bv[CPT];
        #pragma unroll
        for (int k = 0; k < CPT; k++) {
            A[k]  = *(const float4*)(rp + (size_t)k * HW + base0);
            Bv[k] = *(const float4*)(rp + (size_t)k * HW + base1);
        }
        float a0 = w0[i*3], a1 = w0[i*3+1], a2 = w0[i*3+2];
        float b0 = w1[i*3], b1 = w1[i*3+1], b2 = w1[i*3+2];
        #pragma unroll
        for (int k = 0; k < CPT; k++) {
            acc0[k] = fmaf(a0, A[k].z,  acc0[k]);
            acc0[k] = fmaf(a1, A[k].w,  acc0[k]);
            acc0[k] = fmaf(a2, Bv[k].x, acc0[k]);
            acc1[k] = fmaf(b0, Bv[k].x, acc1[k]);
            acc1[k] = fmaf(b1, Bv[k].y, acc1[k]);
            acc1[k] = fmaf(b2, Bv[k].z, acc1[k]);
        }
    }

    float* op = out + ((size_t)(b * C + cg * CPT) * OH + oy) * OW + ox0;
    #pragma unroll
    for (int k = 0; k < CPT; k++) {
        op[(size_t)k * OHW] = acc0[k];
        if (has1) op[(size_t)k * OHW + 1] = acc1[k];
    }
}

// ---------------------------------------------------------------------------
extern "C" void kernel_launch(void* const* d_in, const int* in_sizes, int n_in,
                              void* d_out, int out_size) {
    const float* x = (const float*)d_in[0];
    float* out = (float*)d_out;

    dim3 g1(B * H / 4, SPLIT);
    norm_part_kernel<<<g1, 128>>>(x);

    int n2 = B * HW / 4;
    norm_reduce_kernel<<<(n2 + 255) / 256, 256>>>();

    wts_kernel<<<(NPIX + 255) / 256, 256>>>();

    int n4 = B * CG * OH * PAIRS;    // 1,098,240 = 8580 * 128
    gather_kernel<<<n4 / 128, 128>>>(x, out);
}